// round 14
// baseline (speedup 1.0000x reference)
#include <cuda_runtime.h>
#include <cstdint>

#define CC 96
#define HH 256
#define WW 256
#define KK 7

__device__ __forceinline__ void fma2(unsigned long long &d,
                                     unsigned long long a,
                                     unsigned long long b) {
    asm("fma.rn.f32x2 %0, %1, %2, %0;" : "+l"(d) : "l"(a), "l"(b));
}
__device__ __forceinline__ unsigned long long pk2(float lo, float hi) {
    return (unsigned long long)__float_as_uint(lo) |
           ((unsigned long long)__float_as_uint(hi) << 32);
}
__device__ __forceinline__ void upk2(unsigned long long v, float &lo, float &hi) {
    lo = __uint_as_float((unsigned int)(v & 0xffffffffull));
    hi = __uint_as_float((unsigned int)(v >> 32));
}

// blockDim=(64,2), grid=(1,1,nimg). Thread: 4 cols (float4), 128-ROW strip.
// (Exact R2 structure — the session's fastest — with 64->128 row strips:
//  halo amp 1.19->1.09 and a single wave of 768 blocks.)
// Fast path (r < 5/3): folded 12-tap integer-offset conv, 16-slot register
// ring (slot = row & 15, static), prefetch row y+6.
__global__ __launch_bounds__(128) void caxial_kernel(const float* __restrict__ x,
                                                     const float* __restrict__ wh,
                                                     const float* __restrict__ ww,
                                                     const float* __restrict__ rp,
                                                     float* __restrict__ out) {
    const int c  = blockIdx.z % CC;
    const int tx = threadIdx.x;                               // 0..63
    const int x4 = tx * 4;
    const int y0 = threadIdx.y * 128;                         // strip start (0 or 128)
    const float* xc = x   + (size_t)blockIdx.z * (HH * WW);
    float*       oc = out + (size_t)blockIdx.z * (HH * WW);

    float rv = rp[0];
    if (rv < 1.0f) rv = 1.0f;

    float whv[KK], wwv[KK], fri[KK];
    int   k0i[KK];
    #pragma unroll
    for (int i = 0; i < KK; i++) {
        float ofr = (float)(i - 3) * rv;
        float fl  = floorf(ofr);
        k0i[i] = (int)fl + 6;
        fri[i] = ofr - fl;
        whv[i] = wh[c * KK + i];
        wwv[i] = ww[c * KK + i];
    }

    const bool fast = (k0i[0] >= 0) && (k0i[KK - 1] + 1 <= 11);

    if (fast) {
        // Fold 7 bilinear taps into 12 integer-offset weights (dc/dr = k - 6)
        unsigned long long cwh2[12];
        float cww[12];
        #pragma unroll
        for (int k = 0; k < 12; k++) {
            float sh = 0.f, sw = 0.f;
            #pragma unroll
            for (int i = 0; i < KK; i++) {
                if (k0i[i] == k)     { sh += whv[i] * (1.f - fri[i]); sw += wwv[i] * (1.f - fri[i]); }
                if (k0i[i] + 1 == k) { sh += whv[i] * fri[i];         sw += wwv[i] * fri[i]; }
            }
            cwh2[k] = pk2(sh, sh);
            cww[k]  = sw;
        }

        // Register ring: 16 rows, one float4 each. slot(row) = row & 15.
        ulonglong2 ring[16];
        #pragma unroll
        for (int t = -6; t <= 5; t++) {
            int row = y0 + t;
            ulonglong2 v = make_ulonglong2(0ull, 0ull);
            if (row >= 0)   // row < HH always true in prologue (y0 <= 128)
                v = *reinterpret_cast<const ulonglong2*>(xc + (size_t)row * WW + x4);
            ring[(t + 16) & 15] = v;
        }

        const bool pm2 = (tx >= 2), pm1 = (tx >= 1), pp1 = (tx <= 62), pp2 = (tx <= 61);
        const float4 z4 = make_float4(0.f, 0.f, 0.f, 0.f);

        #pragma unroll 1
        for (int half = 0; half < 8; half++) {
            int ybase = y0 + half * 16;
            #pragma unroll
            for (int u = 0; u < 16; u++) {
                int y = ybase + u;
                // Prefetch row y+6 into slot (u+6)&15
                {
                    int row = y + 6;
                    ulonglong2 v = make_ulonglong2(0ull, 0ull);
                    if (row < HH)
                        v = *reinterpret_cast<const ulonglong2*>(xc + (size_t)row * WW + x4);
                    ring[(u + 6) & 15] = v;
                }
                // W-window side loads (center comes from the ring)
                const float* rowp = xc + (size_t)y * WW;
                float4 wm2 = pm2 ? *reinterpret_cast<const float4*>(rowp + x4 - 8) : z4;
                float4 wm1 = pm1 ? *reinterpret_cast<const float4*>(rowp + x4 - 4) : z4;
                float4 wp1 = pp1 ? *reinterpret_cast<const float4*>(rowp + x4 + 4) : z4;
                float4 wp2 = pp2 ? *reinterpret_cast<const float4*>(rowp + x4 + 8) : z4;

                ulonglong2 ctr = ring[u & 15];       // row y
                float c0, c1, c2, c3;
                upk2(ctr.x, c0, c1);
                upk2(ctr.y, c2, c3);

                // identity + H conv (packed f32x2 FMAs)
                unsigned long long acc01 = ctr.x;
                unsigned long long acc23 = ctr.y;
                #pragma unroll
                for (int k = 0; k < 12; k++) {       // row y + (k-6)
                    ulonglong2 rv2 = ring[(u + k + 10) & 15];
                    fma2(acc01, cwh2[k], rv2.x);
                    fma2(acc23, cwh2[k], rv2.y);
                }
                float a0, a1, a2, a3;
                upk2(acc01, a0, a1);
                upk2(acc23, a2, a3);

                // W conv: win[m] = col (x4 - 8 + m)
                float win[20];
                win[0]=wm2.x;  win[1]=wm2.y;  win[2]=wm2.z;  win[3]=wm2.w;
                win[4]=wm1.x;  win[5]=wm1.y;  win[6]=wm1.z;  win[7]=wm1.w;
                win[8]=c0;     win[9]=c1;     win[10]=c2;    win[11]=c3;
                win[12]=wp1.x; win[13]=wp1.y; win[14]=wp1.z; win[15]=wp1.w;
                win[16]=wp2.x; win[17]=wp2.y; win[18]=wp2.z; win[19]=wp2.w;
                #pragma unroll
                for (int k = 0; k < 12; k++) {       // col x + (k-6)
                    float w = cww[k];
                    a0 += w * win[k + 2];
                    a1 += w * win[k + 3];
                    a2 += w * win[k + 4];
                    a3 += w * win[k + 5];
                }

                __stcs(reinterpret_cast<float4*>(oc + (size_t)y * WW + x4),
                       make_float4(a0, a1, a2, a3));
            }
        }
    } else {
        // Generic path: direct 7-tap bilinear gather along both axes.
        #pragma unroll 1
        for (int yy = 0; yy < 128; yy++) {
            int y = y0 + yy;
            float acc[4];
            #pragma unroll
            for (int j = 0; j < 4; j++) acc[j] = xc[(size_t)y * WW + x4 + j];
            #pragma unroll
            for (int i = 0; i < KK; i++) {
                int   d  = k0i[i] - 6;
                float fr = fri[i];
                int r0 = y + d, r1 = r0 + 1;
                #pragma unroll
                for (int j = 0; j < 4; j++) {
                    int col = x4 + j;
                    float s0 = (r0 >= 0 && r0 < HH) ? xc[(size_t)r0 * WW + col] : 0.f;
                    float s1 = (r1 >= 0 && r1 < HH) ? xc[(size_t)r1 * WW + col] : 0.f;
                    acc[j] += whv[i] * (s0 * (1.f - fr) + s1 * fr);
                    int c0i = col + d, c1i = c0i + 1;
                    float t0 = (c0i >= 0 && c0i < WW) ? xc[(size_t)y * WW + c0i] : 0.f;
                    float t1 = (c1i >= 0 && c1i < WW) ? xc[(size_t)y * WW + c1i] : 0.f;
                    acc[j] += wwv[i] * (t0 * (1.f - fr) + t1 * fr);
                }
            }
            #pragma unroll
            for (int j = 0; j < 4; j++) oc[(size_t)y * WW + x4 + j] = acc[j];
        }
    }
}

extern "C" void kernel_launch(void* const* d_in, const int* in_sizes, int n_in,
                              void* d_out, int out_size) {
    const float* x  = (const float*)d_in[0];
    const float* wh = (const float*)d_in[1];
    const float* ww = (const float*)d_in[2];
    const float* r  = (const float*)d_in[3];
    float* out = (float*)d_out;

    int nimg = in_sizes[0] / (HH * WW);   // B*C = 768

    dim3 blk(64, 2, 1);
    dim3 grd(1, 1, nimg);
    caxial_kernel<<<grd, blk>>>(x, wh, ww, r, out);
}

// round 15
// speedup vs baseline: 1.5708x; 1.5708x over previous
#include <cuda_runtime.h>
#include <cstdint>

#define CC 96
#define HH 256
#define WW 256
#define KK 7

__device__ __forceinline__ void fma2(unsigned long long &d,
                                     unsigned long long a,
                                     unsigned long long b) {
    asm("fma.rn.f32x2 %0, %1, %2, %0;" : "+l"(d) : "l"(a), "l"(b));
}
__device__ __forceinline__ unsigned long long pk2(float lo, float hi) {
    return (unsigned long long)__float_as_uint(lo) |
           ((unsigned long long)__float_as_uint(hi) << 32);
}
__device__ __forceinline__ void upk2(unsigned long long v, float &lo, float &hi) {
    lo = __uint_as_float((unsigned int)(v & 0xffffffffull));
    hi = __uint_as_float((unsigned int)(v >> 32));
}

// blockDim=(64,2), grid=(1,1,nimg). Thread: 4 cols (float4), 128-ROW strip.
// R6 body verbatim (12-slot ring, 11 folded taps, 80-reg schedule under
// __launch_bounds__(128,6)); only the strip length changed 64->128:
//   - vertical halo amortization 1.19 -> 1.09 (DRAM reads -9%)
//   - grid 1536 -> 768 blocks = single wave at 6 blocks/SM
__global__ __launch_bounds__(128, 6) void caxial_kernel(const float* __restrict__ x,
                                                        const float* __restrict__ wh,
                                                        const float* __restrict__ ww,
                                                        const float* __restrict__ rp,
                                                        float* __restrict__ out) {
    const int c  = blockIdx.z % CC;
    const int tx = threadIdx.x;                               // 0..63
    const int x4 = tx * 4;
    const int y0 = threadIdx.y * 128;                         // strip start (0 or 128)
    const float* xc = x   + (size_t)blockIdx.z * (HH * WW);
    float*       oc = out + (size_t)blockIdx.z * (HH * WW);

    float rv = rp[0];
    if (rv < 1.0f) rv = 1.0f;

    float whv[KK], wwv[KK], fri[KK];
    int   k0i[KK];
    #pragma unroll
    for (int i = 0; i < KK; i++) {
        float ofr = (float)(i - 3) * rv;
        float fl  = floorf(ofr);
        k0i[i] = (int)fl + 5;                 // tap index base: dr = k - 5
        fri[i] = ofr - fl;
        whv[i] = wh[c * KK + i];
        wwv[i] = ww[c * KK + i];
    }
    // fast: all folded taps fall in k = 0..10  (r < 5/3)
    const bool fast = (k0i[0] >= 0) && (k0i[KK - 1] + 1 <= 10);

    if (fast) {
        // Fold 7 bilinear taps into 11 integer-offset weights (dc/dr = k - 5)
        unsigned long long cwh2[11];
        float cww[11];
        #pragma unroll
        for (int k = 0; k < 11; k++) {
            float sh = 0.f, sw = 0.f;
            #pragma unroll
            for (int i = 0; i < KK; i++) {
                if (k0i[i] == k)     { sh += whv[i] * (1.f - fri[i]); sw += wwv[i] * (1.f - fri[i]); }
                if (k0i[i] + 1 == k) { sh += whv[i] * fri[i];         sw += wwv[i] * fri[i]; }
            }
            cwh2[k] = pk2(sh, sh);
            cww[k]  = sw;
        }

        // 12-slot register ring; slot(row) = (row - y0 + 5) % 12.
        // Prologue: rows y0-5 .. y0+6 fill slots 0..11.
        ulonglong2 ring[12];
        #pragma unroll
        for (int t = -5; t <= 6; t++) {
            int row = y0 + t;
            ulonglong2 v = make_ulonglong2(0ull, 0ull);
            if (row >= 0)   // row < HH always true in prologue (y0 <= 128, t <= 6)
                v = *reinterpret_cast<const ulonglong2*>(xc + (size_t)row * WW + x4);
            ring[t + 5] = v;
        }

        // Side-load predicates: window cols x4-5 .. x4+8
        const bool eSL = (x4 >= 8);           // col  x4-5         (LDG.32)
        const bool eL1 = (x4 >= 4);           // cols x4-4..x4-1   (LDG.128)
        const bool eR1 = (tx <= 62);          // cols x4+4..x4+7   (LDG.128)
        const bool eSR = (tx <= 61);          // col  x4+8         (LDG.32)
        const float4 z4 = make_float4(0.f, 0.f, 0.f, 0.f);

        // Body for row y with ring phase u (compile-time at every call site)
        #define CAX_BODY(yy, uu)                                                          \
        {                                                                                 \
            const int y = (yy);                                                           \
            /* Ring prefetch: row y+6 -> slot (u+11)%12 (row y-6's slot, now dead) */     \
            {                                                                             \
                int row = y + 6;                                                          \
                ulonglong2 v = make_ulonglong2(0ull, 0ull);                               \
                if (row < HH)                                                             \
                    v = *reinterpret_cast<const ulonglong2*>(xc + (size_t)row * WW + x4); \
                ring[((uu) + 11) % 12] = v;                                               \
            }                                                                             \
            /* Side loads for row y (L1/L2 hits; consumed after H conv) */                \
            const float* rowp = xc + (size_t)y * WW;                                      \
            float  sl = eSL ? rowp[x4 - 5] : 0.f;                                         \
            float4 l1 = eL1 ? *reinterpret_cast<const float4*>(rowp + x4 - 4) : z4;       \
            float4 r1 = eR1 ? *reinterpret_cast<const float4*>(rowp + x4 + 4) : z4;       \
            float  sr = eSR ? rowp[x4 + 8] : 0.f;                                         \
                                                                                          \
            ulonglong2 ctr = ring[((uu) + 5) % 12];     /* row y */                       \
            float c0, c1, c2, c3;                                                         \
            upk2(ctr.x, c0, c1);                                                          \
            upk2(ctr.y, c2, c3);                                                          \
                                                                                          \
            unsigned long long acc01 = ctr.x;                                             \
            unsigned long long acc23 = ctr.y;                                             \
            _Pragma("unroll")                                                             \
            for (int k = 0; k < 11; k++) {              /* row y + (k-5) */               \
                ulonglong2 rv2 = ring[((uu) + k) % 12];                                   \
                fma2(acc01, cwh2[k], rv2.x);                                              \
                fma2(acc23, cwh2[k], rv2.y);                                              \
            }                                                                             \
            float a0, a1, a2, a3;                                                         \
            upk2(acc01, a0, a1);                                                          \
            upk2(acc23, a2, a3);                                                          \
                                                                                          \
            float win[14];                                                                \
            win[0]  = sl;                                                                 \
            win[1]  = l1.x; win[2]  = l1.y; win[3]  = l1.z; win[4]  = l1.w;               \
            win[5]  = c0;   win[6]  = c1;   win[7]  = c2;   win[8]  = c3;                 \
            win[9]  = r1.x; win[10] = r1.y; win[11] = r1.z; win[12] = r1.w;               \
            win[13] = sr;                                                                 \
            _Pragma("unroll")                                                             \
            for (int k = 0; k < 11; k++) {              /* col (x4+j)+(k-5) */            \
                float w = cww[k];                                                         \
                a0 += w * win[k];                                                         \
                a1 += w * win[k + 1];                                                     \
                a2 += w * win[k + 2];                                                     \
                a3 += w * win[k + 3];                                                     \
            }                                                                             \
            __stcs(reinterpret_cast<float4*>(oc + (size_t)y * WW + x4),                   \
                   make_float4(a0, a1, a2, a3));                                          \
        }

        #pragma unroll 1
        for (int g = 0; g < 10; g++) {                // 10 groups of 12 rows (120)
            int ybase = y0 + g * 12;
            #pragma unroll
            for (int u = 0; u < 12; u++) {
                CAX_BODY(ybase + u, u)
            }
        }
        {                                             // tail: 8 rows (120..127)
            int ybase = y0 + 120;                     // 120 % 12 == 0 -> same phases
            #pragma unroll
            for (int u = 0; u < 8; u++) {
                CAX_BODY(ybase + u, u)
            }
        }
        #undef CAX_BODY
    } else {
        // Generic path: direct 7-tap bilinear gather along both axes.
        #pragma unroll 1
        for (int yy = 0; yy < 128; yy++) {
            int y = y0 + yy;
            float acc[4];
            #pragma unroll
            for (int j = 0; j < 4; j++) acc[j] = xc[(size_t)y * WW + x4 + j];
            #pragma unroll
            for (int i = 0; i < KK; i++) {
                int   d  = k0i[i] - 5;
                float fr = fri[i];
                int r0 = y + d, r1 = r0 + 1;
                #pragma unroll
                for (int j = 0; j < 4; j++) {
                    int col = x4 + j;
                    float s0 = (r0 >= 0 && r0 < HH) ? xc[(size_t)r0 * WW + col] : 0.f;
                    float s1 = (r1 >= 0 && r1 < HH) ? xc[(size_t)r1 * WW + col] : 0.f;
                    acc[j] += whv[i] * (s0 * (1.f - fr) + s1 * fr);
                    int c0i = col + d, c1i = c0i + 1;
                    float t0 = (c0i >= 0 && c0i < WW) ? xc[(size_t)y * WW + c0i] : 0.f;
                    float t1 = (c1i >= 0 && c1i < WW) ? xc[(size_t)y * WW + c1i] : 0.f;
                    acc[j] += wwv[i] * (t0 * (1.f - fr) + t1 * fr);
                }
            }
            #pragma unroll
            for (int j = 0; j < 4; j++) oc[(size_t)y * WW + x4 + j] = acc[j];
        }
    }
}

extern "C" void kernel_launch(void* const* d_in, const int* in_sizes, int n_in,
                              void* d_out, int out_size) {
    const float* x  = (const float*)d_in[0];
    const float* wh = (const float*)d_in[1];
    const float* ww = (const float*)d_in[2];
    const float* r  = (const float*)d_in[3];
    float* out = (float*)d_out;

    int nimg = in_sizes[0] / (HH * WW);   // B*C = 768

    dim3 blk(64, 2, 1);
    dim3 grd(1, 1, nimg);
    caxial_kernel<<<grd, blk>>>(x, wh, ww, r, out);
}

// round 16
// speedup vs baseline: 2.0004x; 1.2735x over previous
#include <cuda_runtime.h>
#include <cstdint>

#define CC 96
#define HH 256
#define WW 256
#define KK 7

__device__ __forceinline__ void fma2(unsigned long long &d,
                                     unsigned long long a,
                                     unsigned long long b) {
    asm("fma.rn.f32x2 %0, %1, %2, %0;" : "+l"(d) : "l"(a), "l"(b));
}
__device__ __forceinline__ unsigned long long pk2(float lo, float hi) {
    return (unsigned long long)__float_as_uint(lo) |
           ((unsigned long long)__float_as_uint(hi) << 32);
}
__device__ __forceinline__ void upk2(unsigned long long v, float &lo, float &hi) {
    lo = __uint_as_float((unsigned int)(v & 0xffffffffull));
    hi = __uint_as_float((unsigned int)(v >> 32));
}

// blockDim=(64,2), grid=(1,2,nimg). Thread: 4 cols (float4), 64-row strip.
// R6 body verbatim (12-slot ring, 11 folded taps, 80-reg schedule) plus ONE
// new instruction per iteration: prefetch.global.L2 of row y+16. The prefetch
// has no destination register and no scoreboard -> DRAM-level MLP with zero
// register pressure; the real LDG (row y+6) then hits L2 instead of DRAM.
__global__ __launch_bounds__(128, 6) void caxial_kernel(const float* __restrict__ x,
                                                        const float* __restrict__ wh,
                                                        const float* __restrict__ ww,
                                                        const float* __restrict__ rp,
                                                        float* __restrict__ out) {
    const int c  = blockIdx.z % CC;
    const int tx = threadIdx.x;                               // 0..63
    const int strip = blockIdx.y * 2 + threadIdx.y;           // 0..3
    const int x4 = tx * 4;
    const int y0 = strip * 64;
    const float* xc = x   + (size_t)blockIdx.z * (HH * WW);
    float*       oc = out + (size_t)blockIdx.z * (HH * WW);

    float rv = rp[0];
    if (rv < 1.0f) rv = 1.0f;

    float whv[KK], wwv[KK], fri[KK];
    int   k0i[KK];
    #pragma unroll
    for (int i = 0; i < KK; i++) {
        float ofr = (float)(i - 3) * rv;
        float fl  = floorf(ofr);
        k0i[i] = (int)fl + 5;                 // tap index base: dr = k - 5
        fri[i] = ofr - fl;
        whv[i] = wh[c * KK + i];
        wwv[i] = ww[c * KK + i];
    }
    // fast: all folded taps fall in k = 0..10  (r < 5/3)
    const bool fast = (k0i[0] >= 0) && (k0i[KK - 1] + 1 <= 10);

    if (fast) {
        // Fold 7 bilinear taps into 11 integer-offset weights (dc/dr = k - 5)
        unsigned long long cwh2[11];
        float cww[11];
        #pragma unroll
        for (int k = 0; k < 11; k++) {
            float sh = 0.f, sw = 0.f;
            #pragma unroll
            for (int i = 0; i < KK; i++) {
                if (k0i[i] == k)     { sh += whv[i] * (1.f - fri[i]); sw += wwv[i] * (1.f - fri[i]); }
                if (k0i[i] + 1 == k) { sh += whv[i] * fri[i];         sw += wwv[i] * fri[i]; }
            }
            cwh2[k] = pk2(sh, sh);
            cww[k]  = sw;
        }

        // 12-slot register ring; slot(row) = (row - y0 + 5) % 12.
        // Prologue: rows y0-5 .. y0+6 fill slots 0..11.
        ulonglong2 ring[12];
        #pragma unroll
        for (int t = -5; t <= 6; t++) {
            int row = y0 + t;
            ulonglong2 v = make_ulonglong2(0ull, 0ull);
            if (row >= 0)   // row < HH always true in prologue (y0 <= 192, t <= 6)
                v = *reinterpret_cast<const ulonglong2*>(xc + (size_t)row * WW + x4);
            ring[t + 5] = v;
        }

        // Side-load predicates: window cols x4-5 .. x4+8
        const bool eSL = (x4 >= 8);           // col  x4-5         (LDG.32)
        const bool eL1 = (x4 >= 4);           // cols x4-4..x4-1   (LDG.128)
        const bool eR1 = (tx <= 62);          // cols x4+4..x4+7   (LDG.128)
        const bool eSR = (tx <= 61);          // col  x4+8         (LDG.32)
        const float4 z4 = make_float4(0.f, 0.f, 0.f, 0.f);

        // Body for row y with ring phase u (compile-time at every call site)
        #define CAX_BODY(yy, uu)                                                          \
        {                                                                                 \
            const int y = (yy);                                                           \
            /* L2 prefetch: row y+16 (no register, no scoreboard; depth 10) */            \
            {                                                                             \
                int prow = y + 16;                                                        \
                if (prow < HH)                                                            \
                    asm volatile("prefetch.global.L2 [%0];"                               \
                                 :: "l"(xc + (size_t)prow * WW + x4));                    \
            }                                                                             \
            /* Ring prefetch: row y+6 -> slot (u+11)%12 (row y-6's slot, now dead) */     \
            {                                                                             \
                int row = y + 6;                                                          \
                ulonglong2 v = make_ulonglong2(0ull, 0ull);                               \
                if (row < HH)                                                             \
                    v = *reinterpret_cast<const ulonglong2*>(xc + (size_t)row * WW + x4); \
                ring[((uu) + 11) % 12] = v;                                               \
            }                                                                             \
            /* Side loads for row y (L1/L2 hits; consumed after H conv) */                \
            const float* rowp = xc + (size_t)y * WW;                                      \
            float  sl = eSL ? rowp[x4 - 5] : 0.f;                                         \
            float4 l1 = eL1 ? *reinterpret_cast<const float4*>(rowp + x4 - 4) : z4;       \
            float4 r1 = eR1 ? *reinterpret_cast<const float4*>(rowp + x4 + 4) : z4;       \
            float  sr = eSR ? rowp[x4 + 8] : 0.f;                                         \
                                                                                          \
            ulonglong2 ctr = ring[((uu) + 5) % 12];     /* row y */                       \
            float c0, c1, c2, c3;                                                         \
            upk2(ctr.x, c0, c1);                                                          \
            upk2(ctr.y, c2, c3);                                                          \
                                                                                          \
            unsigned long long acc01 = ctr.x;                                             \
            unsigned long long acc23 = ctr.y;                                             \
            _Pragma("unroll")                                                             \
            for (int k = 0; k < 11; k++) {              /* row y + (k-5) */               \
                ulonglong2 rv2 = ring[((uu) + k) % 12];                                   \
                fma2(acc01, cwh2[k], rv2.x);                                              \
                fma2(acc23, cwh2[k], rv2.y);                                              \
            }                                                                             \
            float a0, a1, a2, a3;                                                         \
            upk2(acc01, a0, a1);                                                          \
            upk2(acc23, a2, a3);                                                          \
                                                                                          \
            float win[14];                                                                \
            win[0]  = sl;                                                                 \
            win[1]  = l1.x; win[2]  = l1.y; win[3]  = l1.z; win[4]  = l1.w;               \
            win[5]  = c0;   win[6]  = c1;   win[7]  = c2;   win[8]  = c3;                 \
            win[9]  = r1.x; win[10] = r1.y; win[11] = r1.z; win[12] = r1.w;               \
            win[13] = sr;                                                                 \
            _Pragma("unroll")                                                             \
            for (int k = 0; k < 11; k++) {              /* col (x4+j)+(k-5) */            \
                float w = cww[k];                                                         \
                a0 += w * win[k];                                                         \
                a1 += w * win[k + 1];                                                     \
                a2 += w * win[k + 2];                                                     \
                a3 += w * win[k + 3];                                                     \
            }                                                                             \
            __stcs(reinterpret_cast<float4*>(oc + (size_t)y * WW + x4),                   \
                   make_float4(a0, a1, a2, a3));                                          \
        }

        #pragma unroll 1
        for (int g = 0; g < 5; g++) {                 // 5 groups of 12 rows
            int ybase = y0 + g * 12;
            #pragma unroll
            for (int u = 0; u < 12; u++) {
                CAX_BODY(ybase + u, u)
            }
        }
        {                                             // tail: 4 rows (60..63)
            int ybase = y0 + 60;                      // 60 % 12 == 0 -> same phases
            #pragma unroll
            for (int u = 0; u < 4; u++) {
                CAX_BODY(ybase + u, u)
            }
        }
        #undef CAX_BODY
    } else {
        // Generic path: direct 7-tap bilinear gather along both axes.
        #pragma unroll 1
        for (int yy = 0; yy < 64; yy++) {
            int y = y0 + yy;
            float acc[4];
            #pragma unroll
            for (int j = 0; j < 4; j++) acc[j] = xc[(size_t)y * WW + x4 + j];
            #pragma unroll
            for (int i = 0; i < KK; i++) {
                int   d  = k0i[i] - 5;
                float fr = fri[i];
                int r0 = y + d, r1 = r0 + 1;
                #pragma unroll
                for (int j = 0; j < 4; j++) {
                    int col = x4 + j;
                    float s0 = (r0 >= 0 && r0 < HH) ? xc[(size_t)r0 * WW + col] : 0.f;
                    float s1 = (r1 >= 0 && r1 < HH) ? xc[(size_t)r1 * WW + col] : 0.f;
                    acc[j] += whv[i] * (s0 * (1.f - fr) + s1 * fr);
                    int c0i = col + d, c1i = c0i + 1;
                    float t0 = (c0i >= 0 && c0i < WW) ? xc[(size_t)y * WW + c0i] : 0.f;
                    float t1 = (c1i >= 0 && c1i < WW) ? xc[(size_t)y * WW + c1i] : 0.f;
                    acc[j] += wwv[i] * (t0 * (1.f - fr) + t1 * fr);
                }
            }
            #pragma unroll
            for (int j = 0; j < 4; j++) oc[(size_t)y * WW + x4 + j] = acc[j];
        }
    }
}

extern "C" void kernel_launch(void* const* d_in, const int* in_sizes, int n_in,
                              void* d_out, int out_size) {
    const float* x  = (const float*)d_in[0];
    const float* wh = (const float*)d_in[1];
    const float* ww = (const float*)d_in[2];
    const float* r  = (const float*)d_in[3];
    float* out = (float*)d_out;

    int nimg = in_sizes[0] / (HH * WW);   // B*C = 768

    dim3 blk(64, 2, 1);
    dim3 grd(1, 2, nimg);
    caxial_kernel<<<grd, blk>>>(x, wh, ww, r, out);
}

// round 17
// speedup vs baseline: 2.0870x; 1.0433x over previous
#include <cuda_runtime.h>
#include <cstdint>

#define CC 96
#define HH 256
#define WW 256
#define KK 7

__device__ __forceinline__ void fma2(unsigned long long &d,
                                     unsigned long long a,
                                     unsigned long long b) {
    asm("fma.rn.f32x2 %0, %1, %2, %0;" : "+l"(d) : "l"(a), "l"(b));
}
__device__ __forceinline__ unsigned long long pk2(float lo, float hi) {
    return (unsigned long long)__float_as_uint(lo) |
           ((unsigned long long)__float_as_uint(hi) << 32);
}
__device__ __forceinline__ void upk2(unsigned long long v, float &lo, float &hi) {
    lo = __uint_as_float((unsigned int)(v & 0xffffffffull));
    hi = __uint_as_float((unsigned int)(v >> 32));
}

// blockDim=(64,2), grid=(1,2,nimg). Thread: 4 cols (float4), 64-row strip.
// R16 (the current best: 12-slot ring + 11 folded taps + prefetch.global.L2
// of row y+16) plus ONE change: the two edge scalars (cols x4-5, x4+8) come
// from 2 warp shuffles of neighbor lanes' ring-center registers instead of
// two 4-wavefront scalar-gather LDGs; warp-edge lanes keep a predicated LDG.
__global__ __launch_bounds__(128, 6) void caxial_kernel(const float* __restrict__ x,
                                                        const float* __restrict__ wh,
                                                        const float* __restrict__ ww,
                                                        const float* __restrict__ rp,
                                                        float* __restrict__ out) {
    const int c  = blockIdx.z % CC;
    const int tx = threadIdx.x;                               // 0..63
    const int lane = tx & 31;                                 // lane within warp
    const int strip = blockIdx.y * 2 + threadIdx.y;           // 0..3
    const int x4 = tx * 4;
    const int y0 = strip * 64;
    const float* xc = x   + (size_t)blockIdx.z * (HH * WW);
    float*       oc = out + (size_t)blockIdx.z * (HH * WW);

    float rv = rp[0];
    if (rv < 1.0f) rv = 1.0f;

    float whv[KK], wwv[KK], fri[KK];
    int   k0i[KK];
    #pragma unroll
    for (int i = 0; i < KK; i++) {
        float ofr = (float)(i - 3) * rv;
        float fl  = floorf(ofr);
        k0i[i] = (int)fl + 5;                 // tap index base: dr = k - 5
        fri[i] = ofr - fl;
        whv[i] = wh[c * KK + i];
        wwv[i] = ww[c * KK + i];
    }
    // fast: all folded taps fall in k = 0..10  (r < 5/3)
    const bool fast = (k0i[0] >= 0) && (k0i[KK - 1] + 1 <= 10);

    if (fast) {
        // Fold 7 bilinear taps into 11 integer-offset weights (dc/dr = k - 5)
        unsigned long long cwh2[11];
        float cww[11];
        #pragma unroll
        for (int k = 0; k < 11; k++) {
            float sh = 0.f, sw = 0.f;
            #pragma unroll
            for (int i = 0; i < KK; i++) {
                if (k0i[i] == k)     { sh += whv[i] * (1.f - fri[i]); sw += wwv[i] * (1.f - fri[i]); }
                if (k0i[i] + 1 == k) { sh += whv[i] * fri[i];         sw += wwv[i] * fri[i]; }
            }
            cwh2[k] = pk2(sh, sh);
            cww[k]  = sw;
        }

        // 12-slot register ring; slot(row) = (row - y0 + 5) % 12.
        // Prologue: rows y0-5 .. y0+6 fill slots 0..11.
        ulonglong2 ring[12];
        #pragma unroll
        for (int t = -5; t <= 6; t++) {
            int row = y0 + t;
            ulonglong2 v = make_ulonglong2(0ull, 0ull);
            if (row >= 0)   // row < HH always true in prologue (y0 <= 192, t <= 6)
                v = *reinterpret_cast<const ulonglong2*>(xc + (size_t)row * WW + x4);
            ring[t + 5] = v;
        }

        // Side-load predicates
        const bool eL1 = (x4 >= 4);           // cols x4-4..x4-1   (LDG.128)
        const bool eR1 = (tx <= 62);          // cols x4+4..x4+7   (LDG.128)
        // Edge-scalar fallbacks: only warp-edge lanes load from global.
        const bool eSLg = (lane < 2)  && (x4 >= 8);        // col x4-5
        const bool eSRg = (lane > 29) && (tx <= 61);       // col x4+8
        const float4 z4 = make_float4(0.f, 0.f, 0.f, 0.f);
        const unsigned FULL = 0xffffffffu;

        // Body for row y with ring phase u (compile-time at every call site)
        #define CAX_BODY(yy, uu)                                                          \
        {                                                                                 \
            const int y = (yy);                                                           \
            /* L2 prefetch: row y+16 (no register, no scoreboard; depth 10) */            \
            {                                                                             \
                int prow = y + 16;                                                        \
                if (prow < HH)                                                            \
                    asm volatile("prefetch.global.L2 [%0];"                               \
                                 :: "l"(xc + (size_t)prow * WW + x4));                    \
            }                                                                             \
            /* Ring prefetch: row y+6 -> slot (u+11)%12 (row y-6's slot, now dead) */     \
            {                                                                             \
                int row = y + 6;                                                          \
                ulonglong2 v = make_ulonglong2(0ull, 0ull);                               \
                if (row < HH)                                                             \
                    v = *reinterpret_cast<const ulonglong2*>(xc + (size_t)row * WW + x4); \
                ring[((uu) + 11) % 12] = v;                                               \
            }                                                                             \
            /* Side float4 loads for row y (L1/L2 hits) + edge-lane fallbacks */          \
            const float* rowp = xc + (size_t)y * WW;                                      \
            float4 l1 = eL1 ? *reinterpret_cast<const float4*>(rowp + x4 - 4) : z4;       \
            float4 r1 = eR1 ? *reinterpret_cast<const float4*>(rowp + x4 + 4) : z4;       \
            float slg = eSLg ? rowp[x4 - 5] : 0.f;                                        \
            float srg = eSRg ? rowp[x4 + 8] : 0.f;                                        \
                                                                                          \
            ulonglong2 ctr = ring[((uu) + 5) % 12];     /* row y */                       \
            float c0, c1, c2, c3;                                                         \
            upk2(ctr.x, c0, c1);                                                          \
            upk2(ctr.y, c2, c3);                                                          \
                                                                                          \
            /* Edge scalars via shuffle: sl = lane(tx-2).c3, sr = lane(tx+2).c0 */        \
            float slS = __shfl_up_sync(FULL, c3, 2);                                      \
            float srS = __shfl_down_sync(FULL, c0, 2);                                    \
            float sl = (lane >= 2)  ? slS : slg;                                          \
            float sr = (lane <= 29) ? srS : srg;                                          \
                                                                                          \
            unsigned long long acc01 = ctr.x;                                             \
            unsigned long long acc23 = ctr.y;                                             \
            _Pragma("unroll")                                                             \
            for (int k = 0; k < 11; k++) {              /* row y + (k-5) */               \
                ulonglong2 rv2 = ring[((uu) + k) % 12];                                   \
                fma2(acc01, cwh2[k], rv2.x);                                              \
                fma2(acc23, cwh2[k], rv2.y);                                              \
            }                                                                             \
            float a0, a1, a2, a3;                                                         \
            upk2(acc01, a0, a1);                                                          \
            upk2(acc23, a2, a3);                                                          \
                                                                                          \
            float win[14];                                                                \
            win[0]  = sl;                                                                 \
            win[1]  = l1.x; win[2]  = l1.y; win[3]  = l1.z; win[4]  = l1.w;               \
            win[5]  = c0;   win[6]  = c1;   win[7]  = c2;   win[8]  = c3;                 \
            win[9]  = r1.x; win[10] = r1.y; win[11] = r1.z; win[12] = r1.w;               \
            win[13] = sr;                                                                 \
            _Pragma("unroll")                                                             \
            for (int k = 0; k < 11; k++) {              /* col (x4+j)+(k-5) */            \
                float w = cww[k];                                                         \
                a0 += w * win[k];                                                         \
                a1 += w * win[k + 1];                                                     \
                a2 += w * win[k + 2];                                                     \
                a3 += w * win[k + 3];                                                     \
            }                                                                             \
            __stcs(reinterpret_cast<float4*>(oc + (size_t)y * WW + x4),                   \
                   make_float4(a0, a1, a2, a3));                                          \
        }

        #pragma unroll 1
        for (int g = 0; g < 5; g++) {                 // 5 groups of 12 rows
            int ybase = y0 + g * 12;
            #pragma unroll
            for (int u = 0; u < 12; u++) {
                CAX_BODY(ybase + u, u)
            }
        }
        {                                             // tail: 4 rows (60..63)
            int ybase = y0 + 60;                      // 60 % 12 == 0 -> same phases
            #pragma unroll
            for (int u = 0; u < 4; u++) {
                CAX_BODY(ybase + u, u)
            }
        }
        #undef CAX_BODY
    } else {
        // Generic path: direct 7-tap bilinear gather along both axes.
        #pragma unroll 1
        for (int yy = 0; yy < 64; yy++) {
            int y = y0 + yy;
            float acc[4];
            #pragma unroll
            for (int j = 0; j < 4; j++) acc[j] = xc[(size_t)y * WW + x4 + j];
            #pragma unroll
            for (int i = 0; i < KK; i++) {
                int   d  = k0i[i] - 5;
                float fr = fri[i];
                int r0 = y + d, r1 = r0 + 1;
                #pragma unroll
                for (int j = 0; j < 4; j++) {
                    int col = x4 + j;
                    float s0 = (r0 >= 0 && r0 < HH) ? xc[(size_t)r0 * WW + col] : 0.f;
                    float s1 = (r1 >= 0 && r1 < HH) ? xc[(size_t)r1 * WW + col] : 0.f;
                    acc[j] += whv[i] * (s0 * (1.f - fr) + s1 * fr);
                    int c0i = col + d, c1i = c0i + 1;
                    float t0 = (c0i >= 0 && c0i < WW) ? xc[(size_t)y * WW + c0i] : 0.f;
                    float t1 = (c1i >= 0 && c1i < WW) ? xc[(size_t)y * WW + c1i] : 0.f;
                    acc[j] += wwv[i] * (t0 * (1.f - fr) + t1 * fr);
                }
            }
            #pragma unroll
            for (int j = 0; j < 4; j++) oc[(size_t)y * WW + x4 + j] = acc[j];
        }
    }
}

extern "C" void kernel_launch(void* const* d_in, const int* in_sizes, int n_in,
                              void* d_out, int out_size) {
    const float* x  = (const float*)d_in[0];
    const float* wh = (const float*)d_in[1];
    const float* ww = (const float*)d_in[2];
    const float* r  = (const float*)d_in[3];
    float* out = (float*)d_out;

    int nimg = in_sizes[0] / (HH * WW);   // B*C = 768

    dim3 blk(64, 2, 1);
    dim3 grd(1, 2, nimg);
    caxial_kernel<<<grd, blk>>>(x, wh, ww, r, out);
}